// round 2
// baseline (speedup 1.0000x reference)
#include <cuda_runtime.h>
#include <math.h>

// Problem constants
#define BT   61      // 1 + P(10) + N(50) sequences
#define LL   10      // sequence length
#define EE   128     // embedding dim
#define HH   128     // hidden dim
#define GG   384     // 3*H gates
#define PITCH4 33    // float4 row pitch (132 floats) -> conflict-free LDS.128

// Scratch for final hidden states (no allocation allowed in kernel_launch)
__device__ float g_enc[BT * HH];

// SMEM layout (floats):
//   w_s  : GG * 132 = 50688   (padded weight matrix, reused w_ih -> w_hh)
//   x_s  : LL * EE  = 1280
//   h_s  : HH       = 128
// total 52096 floats = 208384 bytes (gi lives in registers)
#define SMEM_FLOATS (GG*132 + LL*EE + HH)

__global__ __launch_bounds__(128, 1)
void gru_enc_kernel(const int* __restrict__ phr,
                    const int* __restrict__ pos,
                    const int* __restrict__ neg,
                    const float* __restrict__ u_emb,
                    const float* __restrict__ v_emb,
                    const float* __restrict__ w_ih,
                    const float* __restrict__ w_hh,
                    const float* __restrict__ b_ih,
                    const float* __restrict__ b_hh,
                    const float* __restrict__ h0)
{
    extern __shared__ float smem[];
    float* w_s  = smem;
    float* x_s  = w_s + GG * 132;
    float* h_s  = x_s + LL * EE;

    const int t = threadIdx.x;      // 0..127, owns hidden unit t (gates t, t+128, t+256)
    const int b = blockIdx.x;       // 0..60, sequence id

    // ---- gather x[l][:] for this sequence (coalesced 512B rows) ----
    #pragma unroll
    for (int l = 0; l < LL; ++l) {
        int idx;
        const float* table;
        if (b == 0)        { idx = phr[l];                 table = u_emb; }
        else if (b <= 10)  { idx = pos[(b - 1)  * LL + l]; table = v_emb; }
        else               { idx = neg[(b - 11) * LL + l]; table = v_emb; }
        x_s[l * EE + t] = table[(long long)idx * EE + t];
    }

    // ---- stage w_ih into padded SMEM (float4) ----
    {
        float4* w4 = (float4*)w_s;
        const float4* wg = (const float4*)w_ih;
        #pragma unroll
        for (int i = t; i < GG * 32; i += 128) {
            int row = i >> 5, c = i & 31;
            w4[row * PITCH4 + c] = wg[i];
        }
    }
    __syncthreads();

    // ---- gi[l][g] = dot(x[l], w_ih[g]) + b_ih[g]  (kept in registers) ----
    float gi0[LL], gi1[LL], gi2[LL];
    {
        const float4* w4 = (const float4*)w_s;
        const float4* w0 = w4 + (t)       * PITCH4;
        const float4* w1 = w4 + (t + 128) * PITCH4;
        const float4* w2 = w4 + (t + 256) * PITCH4;
        const float bi0 = b_ih[t], bi1 = b_ih[128 + t], bi2 = b_ih[256 + t];
        #pragma unroll
        for (int l = 0; l < LL; ++l) {
            const float4* xr = (const float4*)(x_s + l * EE);
            float4 a0 = make_float4(0.f,0.f,0.f,0.f);
            float4 a1 = a0, a2 = a0;
            #pragma unroll
            for (int k = 0; k < 32; ++k) {
                float4 xv = xr[k];
                float4 p0 = w0[k];
                float4 p1 = w1[k];
                float4 p2 = w2[k];
                a0.x += xv.x * p0.x; a0.y += xv.y * p0.y; a0.z += xv.z * p0.z; a0.w += xv.w * p0.w;
                a1.x += xv.x * p1.x; a1.y += xv.y * p1.y; a1.z += xv.z * p1.z; a1.w += xv.w * p1.w;
                a2.x += xv.x * p2.x; a2.y += xv.y * p2.y; a2.z += xv.z * p2.z; a2.w += xv.w * p2.w;
            }
            gi0[l] = (a0.x + a0.y) + (a0.z + a0.w) + bi0;
            gi1[l] = (a1.x + a1.y) + (a1.z + a1.w) + bi1;
            gi2[l] = (a2.x + a2.y) + (a2.z + a2.w) + bi2;
        }
    }
    __syncthreads();

    // ---- restage SMEM with w_hh ----
    {
        float4* w4 = (float4*)w_s;
        const float4* wg = (const float4*)w_hh;
        #pragma unroll
        for (int i = t; i < GG * 32; i += 128) {
            int row = i >> 5, c = i & 31;
            w4[row * PITCH4 + c] = wg[i];
        }
    }
    h_s[t] = h0[t];
    __syncthreads();

    // ---- GRU scan (10 serial steps) ----
    {
        const float4* w4 = (const float4*)w_s;
        const float4* w0 = w4 + (t)       * PITCH4;
        const float4* w1 = w4 + (t + 128) * PITCH4;
        const float4* w2 = w4 + (t + 256) * PITCH4;
        const float bh0 = b_hh[t], bh1 = b_hh[128 + t], bh2 = b_hh[256 + t];

        #pragma unroll
        for (int l = 0; l < LL; ++l) {
            const float4* hr4 = (const float4*)h_s;
            float4 a0 = make_float4(0.f,0.f,0.f,0.f);
            float4 a1 = a0, a2 = a0;
            #pragma unroll
            for (int k = 0; k < 32; ++k) {
                float4 hv = hr4[k];
                float4 p0 = w0[k];
                float4 p1 = w1[k];
                float4 p2 = w2[k];
                a0.x += hv.x * p0.x; a0.y += hv.y * p0.y; a0.z += hv.z * p0.z; a0.w += hv.w * p0.w;
                a1.x += hv.x * p1.x; a1.y += hv.y * p1.y; a1.z += hv.z * p1.z; a1.w += hv.w * p1.w;
                a2.x += hv.x * p2.x; a2.y += hv.y * p2.y; a2.z += hv.z * p2.z; a2.w += hv.w * p2.w;
            }
            float hr_ = (a0.x + a0.y) + (a0.z + a0.w) + bh0;
            float hz_ = (a1.x + a1.y) + (a1.z + a1.w) + bh1;
            float hn_ = (a2.x + a2.y) + (a2.z + a2.w) + bh2;

            float r = 1.f / (1.f + expf(-(gi0[l] + hr_)));
            float z = 1.f / (1.f + expf(-(gi1[l] + hz_)));
            float n = tanhf(gi2[l] + r * hn_);
            float hold = h_s[t];
            float hnew = (1.f - z) * n + z * hold;

            __syncthreads();
            h_s[t] = hnew;
            __syncthreads();
        }
    }

    g_enc[b * HH + t] = h_s[t];
}

// Single-warp loss kernel:
//   result = log(1 + sum_{neg, s>0} exp(s)) - sum_pos s
__global__ void loss_kernel(float* __restrict__ out)
{
    int lane = threadIdx.x;  // 32 threads
    float n0 = g_enc[lane];
    float n1 = g_enc[lane + 32];
    float n2 = g_enc[lane + 64];
    float n3 = g_enc[lane + 96];

    float pos_loss = 0.f;
    float neg_sum  = 0.f;
    for (int r = 1; r < BT; ++r) {
        const float* e = g_enc + r * HH;
        float s = n0 * e[lane] + n1 * e[lane + 32] + n2 * e[lane + 64] + n3 * e[lane + 96];
        #pragma unroll
        for (int o = 16; o; o >>= 1) s += __shfl_xor_sync(0xffffffffu, s, o);
        s *= (1.0f / 128.0f);
        if (r <= 10) {
            pos_loss += s;
        } else if (s > 0.f) {
            neg_sum += expf(s);
        }
    }
    if (lane == 0) out[0] = logf(1.f + neg_sum) - pos_loss;
}

extern "C" void kernel_launch(void* const* d_in, const int* in_sizes, int n_in,
                              void* d_out, int out_size)
{
    const int*   phr   = (const int*)  d_in[0];
    const int*   pos   = (const int*)  d_in[1];
    const int*   neg   = (const int*)  d_in[2];
    const float* u_emb = (const float*)d_in[3];
    const float* v_emb = (const float*)d_in[4];
    const float* w_ih  = (const float*)d_in[5];
    const float* w_hh  = (const float*)d_in[6];
    const float* b_ih  = (const float*)d_in[7];
    const float* b_hh  = (const float*)d_in[8];
    const float* h0    = (const float*)d_in[9];
    float* out = (float*)d_out;

    const int smem_bytes = SMEM_FLOATS * (int)sizeof(float);
    cudaFuncSetAttribute(gru_enc_kernel,
                         cudaFuncAttributeMaxDynamicSharedMemorySize, smem_bytes);

    gru_enc_kernel<<<BT, 128, smem_bytes>>>(phr, pos, neg, u_emb, v_emb,
                                            w_ih, w_hh, b_ih, b_hh, h0);
    loss_kernel<<<1, 32>>>(out);
}

// round 4
// speedup vs baseline: 2.3036x; 2.3036x over previous
#include <cuda_runtime.h>
#include <math.h>

// Problem constants
#define BT   61      // 1 + P(10) + N(50) sequences
#define LL   10      // sequence length
#define EE   128     // embedding dim
#define HH   128     // hidden dim
#define GG   384     // 3*H gates
#define NTHR 384     // one thread per gate

// Final hidden states (scratch; no allocs allowed)
__device__ float g_enc[BT * HH];

// packed fp32x2 FMA: d = a*b + c elementwise on two fp32 lanes (sm_100+)
#define FMA2(d, a, b, c) \
    asm("fma.rn.f32x2 %0, %1, %2, %3;" : "=l"(d) : "l"(a), "l"(b), "l"(c))

__device__ __forceinline__ float2 unpack2(unsigned long long v) {
    float2 r;
    asm("mov.b64 {%0, %1}, %2;" : "=f"(r.x), "=f"(r.y) : "l"(v));
    return r;
}

struct __align__(16) SmemT {
    float x[LL * EE];    // gathered inputs
    float gi[LL * GG];   // input-gate preactivations
    float gh[GG];        // per-step hidden-gate preactivations
    float h[EE];         // current hidden state
    int   idx[LL];
};

__global__ __launch_bounds__(NTHR, 1)
void gru_enc_kernel(const int* __restrict__ phr,
                    const int* __restrict__ pos,
                    const int* __restrict__ neg,
                    const float* __restrict__ u_emb,
                    const float* __restrict__ v_emb,
                    const float* __restrict__ w_ih,
                    const float* __restrict__ w_hh,
                    const float* __restrict__ b_ih,
                    const float* __restrict__ b_hh,
                    const float* __restrict__ h0)
{
    __shared__ SmemT sm;

    const int t = threadIdx.x;   // gate id 0..383
    const int b = blockIdx.x;    // sequence id 0..60

    // ---- sequence token indices ----
    if (t < LL) {
        int idx;
        if (b == 0)        idx = phr[t];
        else if (b <= 10)  idx = pos[(b - 1)  * LL + t];
        else               idx = neg[(b - 11) * LL + t];
        sm.idx[t] = idx;
    }
    if (t < HH) sm.h[t] = h0[t];
    __syncthreads();

    // ---- gather x[l][:] (coalesced 512B rows): 1280 elems, 384 threads ----
    {
        const float* table = (b == 0) ? u_emb : v_emb;
        for (int i = t; i < LL * EE; i += NTHR) {
            int l = i >> 7, c = i & 127;
            sm.x[i] = table[(long long)sm.idx[l] * EE + c];
        }
    }
    __syncthreads();

    // ---- gi[l][t] = dot(x[l], w_ih[t]) + b_ih[t]; each weight reused 10x ----
    {
        const ulonglong2* wih = (const ulonglong2*)(w_ih + t * EE);
        const float bi = b_ih[t];
        unsigned long long acc[LL];
        #pragma unroll
        for (int l = 0; l < LL; ++l) acc[l] = 0ull;

        #pragma unroll
        for (int k = 0; k < 32; ++k) {          // k-quad: 4 floats = 2 packed pairs
            ulonglong2 w = wih[k];              // LDG.128 (L2-shared across CTAs)
            #pragma unroll
            for (int l = 0; l < LL; ++l) {
                ulonglong2 xv = *(const ulonglong2*)&sm.x[l * EE + k * 4]; // broadcast
                FMA2(acc[l], w.x, xv.x, acc[l]);
                FMA2(acc[l], w.y, xv.y, acc[l]);
            }
        }
        #pragma unroll
        for (int l = 0; l < LL; ++l) {
            float2 f = unpack2(acc[l]);
            sm.gi[l * GG + t] = f.x + f.y + bi;
        }
    }

    // ---- load this gate's w_hh row into registers (128 floats = 64 packed) ----
    ulonglong2 wr[32];
    {
        const ulonglong2* whh = (const ulonglong2*)(w_hh + t * HH);
        #pragma unroll
        for (int k = 0; k < 32; ++k) wr[k] = whh[k];
    }
    const float bh = b_hh[t];
    __syncthreads();

    // ---- GRU scan: 10 serial steps, weights in registers ----
    for (int l = 0; l < LL; ++l) {
        unsigned long long acc = 0ull;
        #pragma unroll
        for (int k = 0; k < 32; ++k) {
            ulonglong2 hv = *(const ulonglong2*)&sm.h[k * 4];  // broadcast LDS.128
            FMA2(acc, wr[k].x, hv.x, acc);
            FMA2(acc, wr[k].y, hv.y, acc);
        }
        float2 f = unpack2(acc);
        sm.gh[t] = f.x + f.y + bh;
        __syncthreads();

        if (t < HH) {
            float hr_ = sm.gh[t];
            float hz_ = sm.gh[t + 128];
            float hn_ = sm.gh[t + 256];
            float ir  = sm.gi[l * GG + t];
            float iz  = sm.gi[l * GG + t + 128];
            float in_ = sm.gi[l * GG + t + 256];

            float r = 1.f / (1.f + expf(-(ir + hr_)));
            float z = 1.f / (1.f + expf(-(iz + hz_)));
            float n = tanhf(in_ + r * hn_);
            sm.h[t] = (1.f - z) * n + z * sm.h[t];
        }
        __syncthreads();
    }

    if (t < HH) g_enc[b * HH + t] = sm.h[t];
}

// Parallel loss: 16 warps, each handles r = 1+w, 17+w, 33+w, 49+w
//   out = log(1 + sum_{neg, s>0} exp(s)) - sum_pos s
__global__ void loss_kernel(float* __restrict__ out)
{
    __shared__ float pos_part[16], neg_part[16];
    const int t = threadIdx.x;          // 0..511
    const int w = t >> 5, lane = t & 31;

    float n0 = g_enc[lane];
    float n1 = g_enc[lane + 32];
    float n2 = g_enc[lane + 64];
    float n3 = g_enc[lane + 96];

    float pos_loss = 0.f, neg_sum = 0.f;
    for (int r = 1 + w; r < BT; r += 16) {
        const float* e = g_enc + r * HH;
        float s = n0 * e[lane] + n1 * e[lane + 32] + n2 * e[lane + 64] + n3 * e[lane + 96];
        #pragma unroll
        for (int o = 16; o; o >>= 1) s += __shfl_xor_sync(0xffffffffu, s, o);
        s *= (1.0f / 128.0f);
        if (r <= 10)      pos_loss += s;
        else if (s > 0.f) neg_sum  += expf(s);
    }
    if (lane == 0) { pos_part[w] = pos_loss; neg_part[w] = neg_sum; }
    __syncthreads();

    if (t == 0) {
        float P = 0.f, N = 0.f;
        #pragma unroll
        for (int i = 0; i < 16; ++i) { P += pos_part[i]; N += neg_part[i]; }
        out[0] = logf(1.f + N) - P;
    }
}

extern "C" void kernel_launch(void* const* d_in, const int* in_sizes, int n_in,
                              void* d_out, int out_size)
{
    const int*   phr   = (const int*)  d_in[0];
    const int*   pos   = (const int*)  d_in[1];
    const int*   neg   = (const int*)  d_in[2];
    const float* u_emb = (const float*)d_in[3];
    const float* v_emb = (const float*)d_in[4];
    const float* w_ih  = (const float*)d_in[5];
    const float* w_hh  = (const float*)d_in[6];
    const float* b_ih  = (const float*)d_in[7];
    const float* b_hh  = (const float*)d_in[8];
    const float* h0    = (const float*)d_in[9];
    float* out = (float*)d_out;

    gru_enc_kernel<<<BT, NTHR>>>(phr, pos, neg, u_emb, v_emb,
                                 w_ih, w_hh, b_ih, b_hh, h0);
    loss_kernel<<<1, 512>>>(out);
}

// round 5
// speedup vs baseline: 2.8580x; 1.2407x over previous
#include <cuda_runtime.h>
#include <math.h>

// Problem constants
#define BT   61      // 1 + P(10) + N(50) sequences
#define LL   10      // sequence length
#define EE   128     // embedding dim
#define HH   128     // hidden dim
#define GG   384     // 3*H gates
#define NTHR 384     // one thread per gate
#define PITCH 33     // float4 pitch per weight row (132 floats) -> conflict-free LDS

// Final hidden states + completion counter (no allocs allowed)
__device__ float g_enc[BT * HH];
__device__ unsigned int g_sync = 0;

// packed fp32x2 FMA: d = a*b + c elementwise on two fp32 lanes (sm_100+)
#define FMA2(d, a, b, c) \
    asm("fma.rn.f32x2 %0, %1, %2, %3;" : "=l"(d) : "l"(a), "l"(b), "l"(c))

__device__ __forceinline__ float2 unpack2(unsigned long long v) {
    float2 r;
    asm("mov.b64 {%0, %1}, %2;" : "=f"(r.x), "=f"(r.y) : "l"(v));
    return r;
}

// Dynamic SMEM layout (floats):
//   w_s  : GG*132 = 50688  (padded weights; staged w_ih, then reused for w_hh)
//   x_s  : LL*EE  = 1280
//   gi_s : LL*GG  = 3840
//   gh_s : GG     = 384
//   h_s  : HH     = 128
//   idx  : 10 ints
#define SMEM_FLOATS (GG*132 + LL*EE + LL*GG + GG + HH)
#define SMEM_BYTES  (SMEM_FLOATS * 4 + LL * 4)

__global__ __launch_bounds__(NTHR, 1)
void gru_fused_kernel(const int* __restrict__ phr,
                      const int* __restrict__ pos,
                      const int* __restrict__ neg,
                      const float* __restrict__ u_emb,
                      const float* __restrict__ v_emb,
                      const float* __restrict__ w_ih,
                      const float* __restrict__ w_hh,
                      const float* __restrict__ b_ih,
                      const float* __restrict__ b_hh,
                      const float* __restrict__ h0,
                      float* __restrict__ out)
{
    extern __shared__ float dsm[];
    float* w_s  = dsm;                    // padded weight tile
    float* x_s  = w_s  + GG * 132;
    float* gi_s = x_s  + LL * EE;
    float* gh_s = gi_s + LL * GG;
    float* h_s  = gh_s + GG;
    int*  idx_s = (int*)(h_s + HH);

    __shared__ float pos_p[12], neg_p[12];
    __shared__ int   s_last;

    const int t = threadIdx.x;   // gate id 0..383
    const int b = blockIdx.x;    // sequence id 0..60

    // ---- sequence token indices + h0 ----
    if (t < LL) {
        int idx;
        if (b == 0)        idx = phr[t];
        else if (b <= 10)  idx = pos[(b - 1)  * LL + t];
        else               idx = neg[(b - 11) * LL + t];
        idx_s[t] = idx;
    }
    if (t < HH) h_s[t] = h0[t];

    // ---- stage w_ih coalesced into padded SMEM ----
    // 12288 float4; each warp writes one full 32-float4 row per iteration.
    {
        float4* w4 = (float4*)w_s;
        const float4* wg = (const float4*)w_ih;
        #pragma unroll
        for (int j = 0; j < 32; ++j) {
            int i = t + j * NTHR;
            int row = i >> 5, c = i & 31;
            w4[row * PITCH + c] = wg[i];       // coalesced LDG.128, conflict-free STS
        }
    }
    __syncthreads();

    // ---- gather x[l][:] (coalesced 512B rows) ----
    {
        const float* table = (b == 0) ? u_emb : v_emb;
        for (int i = t; i < LL * EE; i += NTHR) {
            int l = i >> 7, c = i & 127;
            x_s[i] = table[(long long)idx_s[l] * EE + c];
        }
    }
    __syncthreads();

    // ---- gi[l][t] = dot(x[l], w_ih[t]) + b_ih[t]; weights from SMEM, reused 10x ----
    {
        const ulonglong2* wrow = (const ulonglong2*)w_s + t * PITCH;
        const float bi = b_ih[t];
        unsigned long long acc[LL];
        #pragma unroll
        for (int l = 0; l < LL; ++l) acc[l] = 0ull;

        #pragma unroll
        for (int k = 0; k < 32; ++k) {           // k-quad: 4 floats = 2 packed pairs
            ulonglong2 w = wrow[k];              // conflict-free LDS.128
            #pragma unroll
            for (int l = 0; l < LL; ++l) {
                ulonglong2 xv = *(const ulonglong2*)&x_s[l * EE + k * 4]; // broadcast
                FMA2(acc[l], w.x, xv.x, acc[l]);
                FMA2(acc[l], w.y, xv.y, acc[l]);
            }
        }
        #pragma unroll
        for (int l = 0; l < LL; ++l) {
            float2 f = unpack2(acc[l]);
            gi_s[l * GG + t] = f.x + f.y + bi;
        }
    }
    __syncthreads();

    // ---- restage w_hh coalesced into the same SMEM buffer ----
    {
        float4* w4 = (float4*)w_s;
        const float4* wg = (const float4*)w_hh;
        #pragma unroll
        for (int j = 0; j < 32; ++j) {
            int i = t + j * NTHR;
            int row = i >> 5, c = i & 31;
            w4[row * PITCH + c] = wg[i];
        }
    }
    __syncthreads();

    // ---- copy this gate's w_hh row into registers (conflict-free LDS) ----
    ulonglong2 wr[32];
    {
        const ulonglong2* wrow = (const ulonglong2*)w_s + t * PITCH;
        #pragma unroll
        for (int k = 0; k < 32; ++k) wr[k] = wrow[k];
    }
    const float bh = b_hh[t];
    __syncthreads();

    // ---- GRU scan: 10 serial steps, weights in registers, 2 acc chains ----
    for (int l = 0; l < LL; ++l) {
        unsigned long long accA = 0ull, accB = 0ull;
        #pragma unroll
        for (int k = 0; k < 32; k += 2) {
            ulonglong2 h0v = *(const ulonglong2*)&h_s[k * 4];        // broadcast
            ulonglong2 h1v = *(const ulonglong2*)&h_s[(k + 1) * 4];  // broadcast
            FMA2(accA, wr[k].x,     h0v.x, accA);
            FMA2(accA, wr[k].y,     h0v.y, accA);
            FMA2(accB, wr[k + 1].x, h1v.x, accB);
            FMA2(accB, wr[k + 1].y, h1v.y, accB);
        }
        float2 fa = unpack2(accA), fb = unpack2(accB);
        gh_s[t] = ((fa.x + fa.y) + (fb.x + fb.y)) + bh;
        __syncthreads();

        if (t < HH) {
            float hr_ = gh_s[t];
            float hz_ = gh_s[t + 128];
            float hn_ = gh_s[t + 256];
            float ir  = gi_s[l * GG + t];
            float iz  = gi_s[l * GG + t + 128];
            float in_ = gi_s[l * GG + t + 256];

            float r = 1.f / (1.f + expf(-(ir + hr_)));
            float z = 1.f / (1.f + expf(-(iz + hz_)));
            float n = tanhf(in_ + r * hn_);
            h_s[t] = (1.f - z) * n + z * h_s[t];
        }
        __syncthreads();
    }

    if (t < HH) g_enc[b * HH + t] = h_s[t];

    // ---- last CTA computes the loss (fused; saves a launch) ----
    if (t == 0) {
        __threadfence();
        unsigned int v = atomicAdd(&g_sync, 1u);
        s_last = (v == BT - 1) ? 1 : 0;
    }
    __syncthreads();
    if (!s_last) return;
    __threadfence();   // acquire: make other CTAs' g_enc writes visible

    {
        const int w = t >> 5, lane = t & 31;   // 12 warps
        float n0 = g_enc[lane];
        float n1 = g_enc[lane + 32];
        float n2 = g_enc[lane + 64];
        float n3 = g_enc[lane + 96];

        float pos_loss = 0.f, neg_sum = 0.f;
        for (int r = 1 + w; r < BT; r += 12) {
            const float* e = g_enc + r * HH;
            float s = n0 * e[lane] + n1 * e[lane + 32]
                    + n2 * e[lane + 64] + n3 * e[lane + 96];
            #pragma unroll
            for (int o = 16; o; o >>= 1) s += __shfl_xor_sync(0xffffffffu, s, o);
            s *= (1.0f / 128.0f);
            if (r <= 10)      pos_loss += s;
            else if (s > 0.f) neg_sum  += expf(s);
        }
        if (lane == 0) { pos_p[w] = pos_loss; neg_p[w] = neg_sum; }
        __syncthreads();

        if (t == 0) {
            float P = 0.f, N = 0.f;
            #pragma unroll
            for (int i = 0; i < 12; ++i) { P += pos_p[i]; N += neg_p[i]; }
            out[0] = logf(1.f + N) - P;
            g_sync = 0;   // reset for next graph replay (deterministic)
        }
    }
}

extern "C" void kernel_launch(void* const* d_in, const int* in_sizes, int n_in,
                              void* d_out, int out_size)
{
    const int*   phr   = (const int*)  d_in[0];
    const int*   pos   = (const int*)  d_in[1];
    const int*   neg   = (const int*)  d_in[2];
    const float* u_emb = (const float*)d_in[3];
    const float* v_emb = (const float*)d_in[4];
    const float* w_ih  = (const float*)d_in[5];
    const float* w_hh  = (const float*)d_in[6];
    const float* b_ih  = (const float*)d_in[7];
    const float* b_hh  = (const float*)d_in[8];
    const float* h0    = (const float*)d_in[9];
    float* out = (float*)d_out;

    cudaFuncSetAttribute(gru_fused_kernel,
                         cudaFuncAttributeMaxDynamicSharedMemorySize, SMEM_BYTES);

    gru_fused_kernel<<<BT, NTHR, SMEM_BYTES>>>(phr, pos, neg, u_emb, v_emb,
                                               w_ih, w_hh, b_ih, b_hh, h0, out);
}

// round 6
// speedup vs baseline: 3.0884x; 1.0806x over previous
#include <cuda_runtime.h>
#include <math.h>
#include <stdint.h>

// Problem constants
#define BT   61      // 1 + P(10) + N(50) sequences
#define LL   10      // sequence length
#define EE   128     // embedding dim
#define HH   128     // hidden dim
#define GG   384     // 3*H gates
#define NTHR 384     // one thread per gate
#define QPR  32      // float4 quads per weight row (128 floats)
#define CQ   8       // quads per pipeline chunk
#define RPITCH 9     // float4 pitch per row inside a chunk slot (bank spread)
#define SLOT_F4 (GG * RPITCH)   // 3456 float4 per slot

// Final hidden states + completion counter (no allocs allowed)
__device__ float g_enc[BT * HH];
__device__ unsigned int g_sync = 0;

// packed fp32x2 FMA: d = a*b + c elementwise on two fp32 lanes (sm_100+)
#define FMA2(d, a, b, c) \
    asm("fma.rn.f32x2 %0, %1, %2, %3;" : "=l"(d) : "l"(a), "l"(b), "l"(c))

__device__ __forceinline__ float2 unpack2(unsigned long long v) {
    float2 r;
    asm("mov.b64 {%0, %1}, %2;" : "=f"(r.x), "=f"(r.y) : "l"(v));
    return r;
}

__device__ __forceinline__ void cp16(uint32_t saddr, const void* gaddr) {
    asm volatile("cp.async.ca.shared.global [%0], [%1], 16;" :: "r"(saddr), "l"(gaddr));
}
__device__ __forceinline__ void cp_commit() {
    asm volatile("cp.async.commit_group;");
}
template <int N>
__device__ __forceinline__ void cp_wait() {
    asm volatile("cp.async.wait_group %0;" :: "n"(N));
}

// Dynamic SMEM layout (floats):
//   ws   : 2 * SLOT_F4 * 4 = 27648   (2-slot chunk ring for streamed weights)
//   x_s  : LL*EE  = 1280
//   gi_s : LL*GG  = 3840
//   gh_s : GG     = 384
//   h_s  : HH     = 128
//   idx  : 10 ints
#define SMEM_FLOATS (2*SLOT_F4*4 + LL*EE + LL*GG + GG + HH)
#define SMEM_BYTES  (SMEM_FLOATS * 4 + LL * 4)

__global__ __launch_bounds__(NTHR, 1)
void gru_fused_kernel(const int* __restrict__ phr,
                      const int* __restrict__ pos,
                      const int* __restrict__ neg,
                      const float* __restrict__ u_emb,
                      const float* __restrict__ v_emb,
                      const float* __restrict__ w_ih,
                      const float* __restrict__ w_hh,
                      const float* __restrict__ b_ih,
                      const float* __restrict__ b_hh,
                      const float* __restrict__ h0,
                      float* __restrict__ out)
{
    extern __shared__ float dsm[];
    float* ws_f  = dsm;                          // chunk ring (2 slots)
    float* x_s   = ws_f + 2 * SLOT_F4 * 4;
    float* gi_s  = x_s  + LL * EE;
    float* gh_s  = gi_s + LL * GG;
    float* h_s   = gh_s + GG;
    int*   idx_s = (int*)(h_s + HH);

    __shared__ float pos_p[12], neg_p[12];
    __shared__ int   s_last;

    const int t = threadIdx.x;   // gate id 0..383
    const int b = blockIdx.x;    // sequence id 0..60

    const uint32_t sb = (uint32_t)__cvta_generic_to_shared(ws_f);

    // Per-thread prefetch of one chunk: 8 float4s, coalesced (8 quads/row).
    // chunk < 4 -> w_ih quads [8c, 8c+8); chunk >= 4 -> w_hh quads [8(c-4), ...).
    auto prefetch = [&](int chunk) {
        const float4* src = (chunk < 4) ? (const float4*)w_ih : (const float4*)w_hh;
        const int qbase = (chunk & 3) * CQ;
        const int slot  = chunk & 1;
        #pragma unroll
        for (int j = 0; j < 8; ++j) {
            int i   = t + j * NTHR;
            int row = i >> 3, q = i & 7;
            uint32_t saddr = sb + (uint32_t)((slot * SLOT_F4 + row * RPITCH + q) * 16);
            cp16(saddr, src + (size_t)row * QPR + qbase + q);
        }
        cp_commit();
    };

    // ---- launch first two chunk prefetches immediately (no dependencies) ----
    prefetch(0);
    prefetch(1);

    // ---- sequence token indices + h0 + biases ----
    if (t < LL) {
        int idx;
        if (b == 0)        idx = phr[t];
        else if (b <= 10)  idx = pos[(b - 1)  * LL + t];
        else               idx = neg[(b - 11) * LL + t];
        idx_s[t] = idx;
    }
    if (t < HH) h_s[t] = h0[t];
    const float bi = b_ih[t];
    const float bh = b_hh[t];
    __syncthreads();

    // ---- gather x[l][:] (coalesced 512B rows) ----
    {
        const float* table = (b == 0) ? u_emb : v_emb;
        for (int i = t; i < LL * EE; i += NTHR) {
            int l = i >> 7, c = i & 127;
            x_s[i] = table[(long long)idx_s[l] * EE + c];
        }
    }

    // ---- streamed pipeline: chunks 0-3 feed gi partial sums, 4-7 fill wr regs ----
    unsigned long long acc[LL];
    #pragma unroll
    for (int l = 0; l < LL; ++l) acc[l] = 0ull;
    ulonglong2 wr[QPR];          // w_hh row of this gate (128 floats)

    #pragma unroll
    for (int c = 0; c < 8; ++c) {
        cp_wait<1>();            // chunk c landed (chunk c+1 may be in flight)
        __syncthreads();         // visibility of all threads' async copies (+x_s on c=0)

        const ulonglong2* wrow =
            (const ulonglong2*)(ws_f + (size_t)(c & 1) * SLOT_F4 * 4) + t * RPITCH;

        if (c < 4) {
            // gi partial: quads [8c, 8c+8)
            #pragma unroll
            for (int q = 0; q < CQ; ++q) {
                ulonglong2 w = wrow[q];                 // LDS.128, 4-phase minimum
                const int k = c * CQ + q;               // global quad index
                #pragma unroll
                for (int l = 0; l < LL; ++l) {
                    ulonglong2 xv = *(const ulonglong2*)&x_s[l * EE + k * 4]; // broadcast
                    FMA2(acc[l], w.x, xv.x, acc[l]);
                    FMA2(acc[l], w.y, xv.y, acc[l]);
                }
            }
            if (c == 3) {
                // gi complete: add bias, store
                #pragma unroll
                for (int l = 0; l < LL; ++l) {
                    float2 f = unpack2(acc[l]);
                    gi_s[l * GG + t] = f.x + f.y + bi;
                }
            }
        } else {
            // copy w_hh quads [8(c-4), 8(c-4)+8) into registers
            #pragma unroll
            for (int q = 0; q < CQ; ++q)
                wr[(c - 4) * CQ + q] = wrow[q];
        }

        __syncthreads();         // all reads of slot done before overwrite
        if (c + 2 < 8) prefetch(c + 2);
    }

    // ---- GRU scan: 10 serial steps, weights in registers, 2 acc chains ----
    for (int l = 0; l < LL; ++l) {
        unsigned long long accA = 0ull, accB = 0ull;
        #pragma unroll
        for (int k = 0; k < 32; k += 2) {
            ulonglong2 h0v = *(const ulonglong2*)&h_s[k * 4];        // broadcast
            ulonglong2 h1v = *(const ulonglong2*)&h_s[(k + 1) * 4];  // broadcast
            FMA2(accA, wr[k].x,     h0v.x, accA);
            FMA2(accA, wr[k].y,     h0v.y, accA);
            FMA2(accB, wr[k + 1].x, h1v.x, accB);
            FMA2(accB, wr[k + 1].y, h1v.y, accB);
        }
        float2 fa = unpack2(accA), fb = unpack2(accB);
        gh_s[t] = ((fa.x + fa.y) + (fb.x + fb.y)) + bh;
        __syncthreads();

        if (t < HH) {
            float hr_ = gh_s[t];
            float hz_ = gh_s[t + 128];
            float hn_ = gh_s[t + 256];
            float ir  = gi_s[l * GG + t];
            float iz  = gi_s[l * GG + t + 128];
            float in_ = gi_s[l * GG + t + 256];

            float r = 1.f / (1.f + expf(-(ir + hr_)));
            float z = 1.f / (1.f + expf(-(iz + hz_)));
            float n = tanhf(in_ + r * hn_);
            h_s[t] = (1.f - z) * n + z * h_s[t];
        }
        __syncthreads();
    }

    if (t < HH) g_enc[b * HH + t] = h_s[t];

    // ---- last CTA computes the loss (fused) ----
    if (t == 0) {
        __threadfence();
        unsigned int v = atomicAdd(&g_sync, 1u);
        s_last = (v == BT - 1) ? 1 : 0;
    }
    __syncthreads();
    if (!s_last) return;
    __threadfence();   // acquire: make other CTAs' g_enc writes visible

    {
        const int w = t >> 5, lane = t & 31;   // 12 warps
        float n0 = g_enc[lane];
        float n1 = g_enc[lane + 32];
        float n2 = g_enc[lane + 64];
        float n3 = g_enc[lane + 96];

        float pos_loss = 0.f, neg_sum = 0.f;
        for (int r = 1 + w; r < BT; r += 12) {
            const float* e = g_enc + r * HH;
            float s = n0 * e[lane] + n1 * e[lane + 32]
                    + n2 * e[lane + 64] + n3 * e[lane + 96];
            #pragma unroll
            for (int o = 16; o; o >>= 1) s += __shfl_xor_sync(0xffffffffu, s, o);
            s *= (1.0f / 128.0f);
            if (r <= 10)      pos_loss += s;
            else if (s > 0.f) neg_sum  += expf(s);
        }
        if (lane == 0) { pos_p[w] = pos_loss; neg_p[w] = neg_sum; }
        __syncthreads();

        if (t == 0) {
            float P = 0.f, N = 0.f;
            #pragma unroll
            for (int i = 0; i < 12; ++i) { P += pos_p[i]; N += neg_p[i]; }
            out[0] = logf(1.f + N) - P;
            g_sync = 0;   // reset for next graph replay (deterministic)
        }
    }
}

extern "C" void kernel_launch(void* const* d_in, const int* in_sizes, int n_in,
                              void* d_out, int out_size)
{
    const int*   phr   = (const int*)  d_in[0];
    const int*   pos   = (const int*)  d_in[1];
    const int*   neg   = (const int*)  d_in[2];
    const float* u_emb = (const float*)d_in[3];
    const float* v_emb = (const float*)d_in[4];
    const float* w_ih  = (const float*)d_in[5];
    const float* w_hh  = (const float*)d_in[6];
    const float* b_ih  = (const float*)d_in[7];
    const float* b_hh  = (const float*)d_in[8];
    const float* h0    = (const float*)d_in[9];
    float* out = (float*)d_out;

    cudaFuncSetAttribute(gru_fused_kernel,
                         cudaFuncAttributeMaxDynamicSharedMemorySize, SMEM_BYTES);

    gru_fused_kernel<<<BT, NTHR, SMEM_BYTES>>>(phr, pos, neg, u_emb, v_emb,
                                               w_ih, w_hh, b_ih, b_hh, h0, out);
}

// round 7
// speedup vs baseline: 3.3498x; 1.0846x over previous
#include <cuda_runtime.h>
#include <math.h>
#include <stdint.h>

// Problem constants
#define BT   61      // 1 + P(10) + N(50) sequences
#define LL   10      // sequence length
#define EE   128     // embedding dim
#define HH   128     // hidden dim
#define GG   384     // 3*H gates
#define NTHR 384     // one thread per gate
#define QPR  32      // float4 quads per weight row (128 floats)
#define CQ   8       // quads per pipeline chunk
#define RPITCH 9     // float4 pitch per row inside a chunk slot (bank spread)
#define SLOT_F4 (GG * RPITCH)   // 3456 float4 per slot
#define NSLOT 3

// Cross-CTA state (no allocs allowed). All reset by the last CTA each run.
__device__ float g_node[HH];
__device__ int   g_flag = 0;
__device__ float g_pos  = 0.f;
__device__ float g_neg  = 0.f;
__device__ unsigned int g_sync = 0;

// packed fp32x2 FMA: d = a*b + c elementwise on two fp32 lanes (sm_100+)
#define FMA2(d, a, b, c) \
    asm("fma.rn.f32x2 %0, %1, %2, %3;" : "=l"(d) : "l"(a), "l"(b), "l"(c))

__device__ __forceinline__ float2 unpack2(unsigned long long v) {
    float2 r;
    asm("mov.b64 {%0, %1}, %2;" : "=f"(r.x), "=f"(r.y) : "l"(v));
    return r;
}
__device__ __forceinline__ float tanh_apx(float x) {
    float y;
    asm("tanh.approx.f32 %0, %1;" : "=f"(y) : "f"(x));
    return y;
}
__device__ __forceinline__ float sig_apx(float x) {
    return 0.5f * tanh_apx(0.5f * x) + 0.5f;
}
__device__ __forceinline__ void cp16(uint32_t saddr, const void* gaddr) {
    asm volatile("cp.async.ca.shared.global [%0], [%1], 16;" :: "r"(saddr), "l"(gaddr));
}
__device__ __forceinline__ void cp_commit() {
    asm volatile("cp.async.commit_group;");
}
template <int N>
__device__ __forceinline__ void cp_wait() {
    asm volatile("cp.async.wait_group %0;" :: "n"(N));
}
__device__ __forceinline__ float ldcg(const float* p) {
    float v;
    asm volatile("ld.global.cg.f32 %0, [%1];" : "=f"(v) : "l"(p));
    return v;
}

// Dynamic SMEM layout (floats):
//   ws   : 3 * SLOT_F4 * 4 = 41472   (3-slot chunk ring for streamed weights)
//   x_s  : LL*EE  = 1280
//   gi_s : LL*GG  = 3840
//   gh_s : GG     = 384   (also reused as reduction scratch)
//   h_s  : HH     = 128
#define SMEM_FLOATS (NSLOT*SLOT_F4*4 + LL*EE + LL*GG + GG + HH)
#define SMEM_BYTES  (SMEM_FLOATS * 4)

__global__ __launch_bounds__(NTHR, 1)
void gru_fused_kernel(const int* __restrict__ phr,
                      const int* __restrict__ pos,
                      const int* __restrict__ neg,
                      const float* __restrict__ u_emb,
                      const float* __restrict__ v_emb,
                      const float* __restrict__ w_ih,
                      const float* __restrict__ w_hh,
                      const float* __restrict__ b_ih,
                      const float* __restrict__ b_hh,
                      const float* __restrict__ h0,
                      float* __restrict__ out)
{
    extern __shared__ float dsm[];
    float* ws_f  = dsm;                          // chunk ring (3 slots)
    float* x_s   = ws_f + NSLOT * SLOT_F4 * 4;
    float* gi_s  = x_s  + LL * EE;
    float* gh_s  = gi_s + LL * GG;
    float* h_s   = gh_s + GG;

    const int t = threadIdx.x;   // gate id 0..383
    const int b = blockIdx.x;    // sequence id 0..60

    const uint32_t sb = (uint32_t)__cvta_generic_to_shared(ws_f);

    // Per-thread prefetch of one chunk: 8 float4s, coalesced (8 quads/row).
    // chunk < 4 -> w_ih quads [8c, 8c+8); chunk >= 4 -> w_hh quads [8(c-4), ...).
    auto prefetch = [&](int chunk) {
        const float4* src = (chunk < 4) ? (const float4*)w_ih : (const float4*)w_hh;
        const int qbase = (chunk & 3) * CQ;
        const int slot  = chunk % NSLOT;
        #pragma unroll
        for (int j = 0; j < 8; ++j) {
            int i   = t + j * NTHR;
            int row = i >> 3, q = i & 7;
            uint32_t saddr = sb + (uint32_t)((slot * SLOT_F4 + row * RPITCH + q) * 16);
            cp16(saddr, src + (size_t)row * QPR + qbase + q);
        }
        cp_commit();
    };

    // ---- gather x (latency-critical; redundant idx loads broadcast via L1) ----
    {
        const float* table = (b == 0) ? u_emb : v_emb;
        const int* ip = (b == 0) ? phr : (b <= 10 ? pos + (b - 1) * LL
                                                  : neg + (b - 11) * LL);
        #pragma unroll
        for (int i = t; i < LL * EE; i += NTHR) {
            int l = i >> 7, c = i & 127;
            int idx = __ldg(ip + l);
            x_s[i] = table[(long long)idx * EE + c];
        }
    }

    // ---- launch first two chunk prefetches ----
    prefetch(0);
    prefetch(1);

    if (t < HH) h_s[t] = h0[t];
    const float bi = b_ih[t];
    const float bh = b_hh[t];

    // ---- streamed pipeline: chunks 0-3 feed gi partial sums, 4-7 fill wr regs ----
    unsigned long long acc[LL];
    #pragma unroll
    for (int l = 0; l < LL; ++l) acc[l] = 0ull;
    ulonglong2 wr[QPR];          // w_hh row of this gate (128 floats)

    #pragma unroll
    for (int c = 0; c < 8; ++c) {
        cp_wait<1>();            // my copies for chunk c done (c+1 may fly)
        __syncthreads();         // everyone's chunk-c copies visible (+x_s on c=0)
        if (c + 2 < 8) prefetch(c + 2);   // slot (c+2)%3: last read iter c-1, safe

        const ulonglong2* wrow =
            (const ulonglong2*)(ws_f + (size_t)(c % NSLOT) * SLOT_F4 * 4) + t * RPITCH;

        if (c < 4) {
            #pragma unroll
            for (int q = 0; q < CQ; ++q) {
                ulonglong2 w = wrow[q];                 // LDS.128
                const int k = c * CQ + q;               // global quad index
                #pragma unroll
                for (int l = 0; l < LL; ++l) {
                    ulonglong2 xv = *(const ulonglong2*)&x_s[l * EE + k * 4]; // bcast
                    FMA2(acc[l], w.x, xv.x, acc[l]);
                    FMA2(acc[l], w.y, xv.y, acc[l]);
                }
            }
            if (c == 3) {
                #pragma unroll
                for (int l = 0; l < LL; ++l) {
                    float2 f = unpack2(acc[l]);
                    gi_s[l * GG + t] = f.x + f.y + bi;
                }
            }
        } else {
            #pragma unroll
            for (int q = 0; q < CQ; ++q)
                wr[(c - 4) * CQ + q] = wrow[q];
        }
    }
    __syncthreads();             // gi_s / wr complete before scan

    // ---- GRU scan: 10 serial steps, weights in registers, approx nonlinearity ----
    for (int l = 0; l < LL; ++l) {
        unsigned long long accA = 0ull, accB = 0ull;
        #pragma unroll
        for (int k = 0; k < 32; k += 2) {
            ulonglong2 h0v = *(const ulonglong2*)&h_s[k * 4];        // bcast
            ulonglong2 h1v = *(const ulonglong2*)&h_s[(k + 1) * 4];  // bcast
            FMA2(accA, wr[k].x,     h0v.x, accA);
            FMA2(accA, wr[k].y,     h0v.y, accA);
            FMA2(accB, wr[k + 1].x, h1v.x, accB);
            FMA2(accB, wr[k + 1].y, h1v.y, accB);
        }
        float2 fa = unpack2(accA), fb = unpack2(accB);
        gh_s[t] = ((fa.x + fa.y) + (fb.x + fb.y)) + bh;
        __syncthreads();

        if (t < HH) {
            float hr_ = gh_s[t];
            float hz_ = gh_s[t + 128];
            float hn_ = gh_s[t + 256];
            float ir  = gi_s[l * GG + t];
            float iz  = gi_s[l * GG + t + 128];
            float in_ = gi_s[l * GG + t + 256];

            float r = sig_apx(ir + hr_);
            float z = sig_apx(iz + hz_);
            float n = tanh_apx(in_ + r * hn_);
            h_s[t] = z * (h_s[t] - n) + n;     // (1-z)n + z h
        }
        __syncthreads();
    }

    // ---- distributed loss ----
    if (b == 0) {
        // publish node
        if (t < HH) g_node[t] = h_s[t];
        __syncthreads();
        if (t == 0) {
            __threadfence();
            asm volatile("st.global.release.gpu.b32 [%0], %1;"
                         :: "l"(&g_flag), "r"(1) : "memory");
        }
    } else {
        // wait for node, then dot with our own h
        if (t == 0) {
            int f;
            do {
                asm volatile("ld.global.acquire.gpu.b32 %0, [%1];"
                             : "=r"(f) : "l"(&g_flag) : "memory");
            } while (!f);
        }
        __syncthreads();

        if (t < HH) {
            float p = ldcg(&g_node[t]) * h_s[t];
            #pragma unroll
            for (int o = 16; o; o >>= 1) p += __shfl_xor_sync(0xffffffffu, p, o);
            if ((t & 31) == 0) gh_s[t >> 5] = p;   // 4 warp partials
        }
        __syncthreads();
        if (t == 0) {
            float s = (gh_s[0] + gh_s[1] + gh_s[2] + gh_s[3]) * (1.0f / 128.0f);
            if (b <= 10)      atomicAdd(&g_pos, s);
            else if (s > 0.f) atomicAdd(&g_neg, __expf(s));
        }
    }

    // ---- last CTA finalizes and resets globals for next replay ----
    if (t == 0) {
        __threadfence();
        unsigned int v = atomicAdd(&g_sync, 1u);
        if (v == BT - 1) {
            out[0] = logf(1.f + g_neg) - g_pos;
            g_pos = 0.f;
            g_neg = 0.f;
            g_flag = 0;
            g_sync = 0;
        }
    }
}

extern "C" void kernel_launch(void* const* d_in, const int* in_sizes, int n_in,
                              void* d_out, int out_size)
{
    const int*   phr   = (const int*)  d_in[0];
    const int*   pos   = (const int*)  d_in[1];
    const int*   neg   = (const int*)  d_in[2];
    const float* u_emb = (const float*)d_in[3];
    const float* v_emb = (const float*)d_in[4];
    const float* w_ih  = (const float*)d_in[5];
    const float* w_hh  = (const float*)d_in[6];
    const float* b_ih  = (const float*)d_in[7];
    const float* b_hh  = (const float*)d_in[8];
    const float* h0    = (const float*)d_in[9];
    float* out = (float*)d_out;

    cudaFuncSetAttribute(gru_fused_kernel,
                         cudaFuncAttributeMaxDynamicSharedMemorySize, SMEM_BYTES);

    gru_fused_kernel<<<BT, NTHR, SMEM_BYTES>>>(phr, pos, neg, u_emb, v_emb,
                                               w_ih, w_hh, b_ih, b_hh, h0, out);
}

// round 8
// speedup vs baseline: 3.3545x; 1.0014x over previous
#include <cuda_runtime.h>
#include <math.h>
#include <stdint.h>

// Problem constants
#define BT   61      // 1 + P(10) + N(50) sequences
#define LL   10      // sequence length
#define EE   128     // embedding dim
#define HH   128     // hidden dim
#define GG   384     // 3*H gates
#define NTHR 384
#define QPR  32      // float4 quads per weight row (128 floats)
#define CQ   8       // quads per pipeline chunk
#define RPITCH 10    // float4 pitch per row inside a chunk slot
#define SLOT_F4 (GG * RPITCH)   // 3840 float4 per slot
#define NSLOT 3

// Cross-CTA state (no allocs allowed). All reset by the last CTA each run.
__device__ float g_node[HH];
__device__ int   g_flag = 0;
__device__ float g_pos  = 0.f;
__device__ float g_neg  = 0.f;
__device__ unsigned int g_sync = 0;

// packed fp32x2 FMA: d = a*b + c elementwise on two fp32 lanes (sm_100+)
#define FMA2(d, a, b, c) \
    asm("fma.rn.f32x2 %0, %1, %2, %3;" : "=l"(d) : "l"(a), "l"(b), "l"(c))

__device__ __forceinline__ float2 unpack2(unsigned long long v) {
    float2 r;
    asm("mov.b64 {%0, %1}, %2;" : "=f"(r.x), "=f"(r.y) : "l"(v));
    return r;
}
__device__ __forceinline__ float tanh_apx(float x) {
    float y;
    asm("tanh.approx.f32 %0, %1;" : "=f"(y) : "f"(x));
    return y;
}
__device__ __forceinline__ float sig_apx(float x) {
    return 0.5f * tanh_apx(0.5f * x) + 0.5f;
}
__device__ __forceinline__ void cp16(uint32_t saddr, const void* gaddr) {
    asm volatile("cp.async.ca.shared.global [%0], [%1], 16;" :: "r"(saddr), "l"(gaddr));
}
__device__ __forceinline__ void cp_commit() {
    asm volatile("cp.async.commit_group;");
}
template <int N>
__device__ __forceinline__ void cp_wait() {
    asm volatile("cp.async.wait_group %0;" :: "n"(N));
}
__device__ __forceinline__ float ldcg(const float* p) {
    float v;
    asm volatile("ld.global.cg.f32 %0, [%1];" : "=f"(v) : "l"(p));
    return v;
}

// Dynamic SMEM layout (floats):
//   ws   : 3 * SLOT_F4 * 4 = 46080   (3-slot chunk ring, pitch-10 rows)
//   x_s  : LL*EE  = 1280
//   gi_s : LL*GG  = 3840
//   gh_s : GG     = 384   (also reduction scratch)
//   h_s  : HH     = 128
#define SMEM_FLOATS (NSLOT*SLOT_F4*4 + LL*EE + LL*GG + GG + HH)
#define SMEM_BYTES  (SMEM_FLOATS * 4)

__global__ __launch_bounds__(NTHR, 1)
void gru_fused_kernel(const int* __restrict__ phr,
                      const int* __restrict__ pos,
                      const int* __restrict__ neg,
                      const float* __restrict__ u_emb,
                      const float* __restrict__ v_emb,
                      const float* __restrict__ w_ih,
                      const float* __restrict__ w_hh,
                      const float* __restrict__ b_ih,
                      const float* __restrict__ b_hh,
                      const float* __restrict__ h0,
                      float* __restrict__ out)
{
    extern __shared__ float dsm[];
    float* ws_f  = dsm;                          // chunk ring (3 slots)
    float* x_s   = ws_f + NSLOT * SLOT_F4 * 4;
    float* gi_s  = x_s  + LL * EE;
    float* gh_s  = gi_s + LL * GG;
    float* h_s   = gh_s + GG;

    const int t = threadIdx.x;   // 0..383
    const int b = blockIdx.x;    // sequence id 0..60

    const uint32_t sb = (uint32_t)__cvta_generic_to_shared(ws_f);

    // Per-thread prefetch of one chunk: 8 float4s, coalesced (8 quads/row).
    // chunk < 4 -> w_ih quads [8c, 8c+8); chunk >= 4 -> w_hh quads [8(c-4), ...).
    auto prefetch = [&](int chunk) {
        const float4* src = (chunk < 4) ? (const float4*)w_ih : (const float4*)w_hh;
        const int qbase = (chunk & 3) * CQ;
        const int slot  = chunk % NSLOT;
        #pragma unroll
        for (int j = 0; j < 8; ++j) {
            int i   = t + j * NTHR;
            int row = i >> 3, q = i & 7;
            uint32_t saddr = sb + (uint32_t)((slot * SLOT_F4 + row * RPITCH + q) * 16);
            cp16(saddr, src + (size_t)row * QPR + qbase + q);
        }
        cp_commit();
    };

    // ---- gather x (latency-critical; redundant idx loads broadcast via L1) ----
    {
        const float* table = (b == 0) ? u_emb : v_emb;
        const int* ip = (b == 0) ? phr : (b <= 10 ? pos + (b - 1) * LL
                                                  : neg + (b - 11) * LL);
        #pragma unroll
        for (int i = t; i < LL * EE; i += NTHR) {
            int l = i >> 7, c = i & 127;
            int idx = __ldg(ip + l);
            x_s[i] = table[(long long)idx * EE + c];
        }
    }

    // ---- launch first two chunk prefetches ----
    prefetch(0);
    prefetch(1);

    if (t < HH) h_s[t] = h0[t];
    const float bh = b_hh[t];

    // gi pair mapping: thread t covers gates gA = t>>1 and gB = t>>1 + 192,
    // over quad-parity hf = t&1 (quads hf, hf+2, ... within each chunk).
    const int hf = t & 1;
    const int gA = t >> 1;
    const int gB = (t >> 1) + 192;
    const float biA = b_ih[gA];
    const float biB = b_ih[gB];

    unsigned long long accA[LL], accB[LL];
    #pragma unroll
    for (int l = 0; l < LL; ++l) { accA[l] = 0ull; accB[l] = 0ull; }
    ulonglong2 wr[QPR];          // w_hh row of gate t (128 floats), for the scan

    #pragma unroll
    for (int c = 0; c < 8; ++c) {
        cp_wait<1>();            // my copies for chunk c done (c+1 may fly)
        __syncthreads();         // everyone's chunk-c copies visible (+x_s on c=0)
        if (c + 2 < 8) prefetch(c + 2);   // slot (c+2)%3: last read iter c-1, safe

        const float* slotp = ws_f + (size_t)(c % NSLOT) * SLOT_F4 * 4;

        if (c < 4) {
            const ulonglong2* wA = (const ulonglong2*)slotp + gA * RPITCH;
            const ulonglong2* wB = (const ulonglong2*)slotp + gB * RPITCH;
            #pragma unroll
            for (int qi = 0; qi < 4; ++qi) {
                const int ql = 2 * qi + hf;         // local quad (parity split)
                const int k  = c * CQ + ql;         // global quad index
                ulonglong2 wa = wA[ql];
                ulonglong2 wb = wB[ql];
                #pragma unroll
                for (int l = 0; l < LL; ++l) {
                    ulonglong2 xv = *(const ulonglong2*)&x_s[l * EE + k * 4];
                    FMA2(accA[l], wa.x, xv.x, accA[l]);
                    FMA2(accA[l], wa.y, xv.y, accA[l]);
                    FMA2(accB[l], wb.x, xv.x, accB[l]);
                    FMA2(accB[l], wb.y, xv.y, accB[l]);
                }
            }
            if (c == 3) {
                // combine k-halves across lane pairs, add bias, store
                #pragma unroll
                for (int l = 0; l < LL; ++l) {
                    float2 fa = unpack2(accA[l]);
                    float2 fb = unpack2(accB[l]);
                    float sA = fa.x + fa.y;
                    float sB = fb.x + fb.y;
                    sA += __shfl_xor_sync(0xffffffffu, sA, 1);
                    sB += __shfl_xor_sync(0xffffffffu, sB, 1);
                    if (hf == 0) gi_s[l * GG + gA] = sA + biA;
                    else         gi_s[l * GG + gB] = sB + biB;
                }
            }
        } else {
            const ulonglong2* wrow = (const ulonglong2*)slotp + t * RPITCH;
            #pragma unroll
            for (int q = 0; q < CQ; ++q)
                wr[(c - 4) * CQ + q] = wrow[q];
        }
    }
    __syncthreads();             // gi_s / wr complete before scan

    // ---- GRU scan: thread t owns gate t (full k); t<128 keeps h in register ----
    float hreg = (t < HH) ? h_s[t] : 0.f;

    for (int l = 0; l < LL; ++l) {
        unsigned long long dA = 0ull, dB = 0ull;
        #pragma unroll
        for (int k = 0; k < 32; k += 2) {
            ulonglong2 h0v = *(const ulonglong2*)&h_s[k * 4];        // bcast
            ulonglong2 h1v = *(const ulonglong2*)&h_s[(k + 1) * 4];  // bcast
            FMA2(dA, wr[k].x,     h0v.x, dA);
            FMA2(dA, wr[k].y,     h0v.y, dA);
            FMA2(dB, wr[k + 1].x, h1v.x, dB);
            FMA2(dB, wr[k + 1].y, h1v.y, dB);
        }
        float2 fa = unpack2(dA), fb = unpack2(dB);
        float ghv = ((fa.x + fa.y) + (fb.x + fb.y)) + bh;

        float r = 0.f, izv = 0.f, inv = 0.f;
        if (t < HH) {
            // static loads (gi_s stable) + r off the critical path
            float irv = gi_s[l * GG + t];
            izv = gi_s[l * GG + t + 128];
            inv = gi_s[l * GG + t + 256];
            r = sig_apx(irv + ghv);            // hr_ is our own dot result
        } else {
            gh_s[t] = ghv;                     // only t>=128 publish gh
        }
        __syncthreads();

        if (t < HH) {
            float hz = gh_s[t + 128];
            float hn = gh_s[t + 256];
            float z = sig_apx(izv + hz);
            float n = tanh_apx(fmaf(r, hn, inv));
            hreg = fmaf(z, hreg - n, n);       // (1-z)n + z h
            h_s[t] = hreg;
        }
        __syncthreads();
    }

    // ---- distributed loss ----
    if (b == 0) {
        if (t < HH) g_node[t] = hreg;
        __syncthreads();
        if (t == 0) {
            __threadfence();
            asm volatile("st.global.release.gpu.b32 [%0], %1;"
                         :: "l"(&g_flag), "r"(1) : "memory");
        }
    } else {
        if (t == 0) {
            int f;
            do {
                asm volatile("ld.global.acquire.gpu.b32 %0, [%1];"
                             : "=r"(f) : "l"(&g_flag) : "memory");
            } while (!f);
        }
        __syncthreads();

        if (t < HH) {
            float p = ldcg(&g_node[t]) * hreg;
            #pragma unroll
            for (int o = 16; o; o >>= 1) p += __shfl_xor_sync(0xffffffffu, p, o);
            if ((t & 31) == 0) gh_s[t >> 5] = p;   // 4 warp partials
        }
        __syncthreads();
        if (t == 0) {
            float s = (gh_s[0] + gh_s[1] + gh_s[2] + gh_s[3]) * (1.0f / 128.0f);
            if (b <= 10)      atomicAdd(&g_pos, s);
            else if (s > 0.f) atomicAdd(&g_neg, __expf(s));
        }
    }

    // ---- last CTA finalizes and resets globals for next replay ----
    if (t == 0) {
        __threadfence();
        unsigned int v = atomicAdd(&g_sync, 1u);
        if (v == BT - 1) {
            out[0] = logf(1.f + g_neg) - g_pos;
            g_pos = 0.f;
            g_neg = 0.f;
            g_flag = 0;
            g_sync = 0;
        }
    }
}

extern "C" void kernel_launch(void* const* d_in, const int* in_sizes, int n_in,
                              void* d_out, int out_size)
{
    const int*   phr   = (const int*)  d_in[0];
    const int*   pos   = (const int*)  d_in[1];
    const int*   neg   = (const int*)  d_in[2];
    const float* u_emb = (const float*)d_in[3];
    const float* v_emb = (const float*)d_in[4];
    const float* w_ih  = (const float*)d_in[5];
    const float* w_hh  = (const float*)d_in[6];
    const float* b_ih  = (const float*)d_in[7];
    const float* b_hh  = (const float*)d_in[8];
    const float* h0    = (const float*)d_in[9];
    float* out = (float*)d_out;

    cudaFuncSetAttribute(gru_fused_kernel,
                         cudaFuncAttributeMaxDynamicSharedMemorySize, SMEM_BYTES);

    gru_fused_kernel<<<BT, NTHR, SMEM_BYTES>>>(phr, pos, neg, u_emb, v_emb,
                                               w_ih, w_hh, b_ih, b_hh, h0, out);
}